// round 10
// baseline (speedup 1.0000x reference)
#include <cuda_runtime.h>
#include <cuda_bf16.h>

// Embedder R8: two launches, both full-grid (avoid B300 low-grid throttle).
//   main:  per-block affine fold (threads 0..15 -> smem), then 8 float4s per
//          thread. token -> __ldcg 256B gather (table stays L2-resident since
//          output stores are __stcs evict-first). numeric -> A*x+C exact for
//          x >= xguard; rare below-guard positions appended to g_fix_list.
//   fixup: 148 blocks grid-stride over the recorded list (exact MLP
//          overwrite). Last block to finish resets the counters ->
//          graph-replay safe, no prep launch, no single-CTA kernel anywhere.

#define HIDDEN 16
#define NPOS   (128 * 4096)
#define IT     8                      // float4s per thread in main
#define FIXUP_BLOCKS 148

__device__ int g_fix_count;          // zero-initialized at module load
__device__ int g_done;               // zero-initialized at module load
__device__ int g_fix_list[NPOS];

__global__ void __launch_bounds__(256) embedder_kernel(
    const float* __restrict__ input_ids,
    const int* __restrict__ type_mask,
    const float4* __restrict__ emb_table,   // [VOCAB][16] float4
    const float* __restrict__ w1,
    const float* __restrict__ b1,
    const float* __restrict__ w2,           // [64][16]
    const float* __restrict__ b2,
    float4* __restrict__ out,
    int n_vec)
{
    __shared__ float4 sA[16];
    __shared__ float4 sC[16];
    __shared__ float  sXg;

    // ---- per-block affine fold (threads 0..15), L1/L2-hot after block 0 ----
    if (threadIdx.x < 16) {
        int q  = threadIdx.x;
        int d0 = q * 4;
        float A[4] = {0.f, 0.f, 0.f, 0.f};
        float C[4] = {b2[d0], b2[d0+1], b2[d0+2], b2[d0+3]};
        float xlo = -3.4e38f;
        #pragma unroll
        for (int j = 0; j < HIDDEN; j++) {
            float w1j = w1[j], b1j = b1[j];
            if (w1j != 0.f) xlo = fmaxf(xlo, -b1j / w1j);
            #pragma unroll
            for (int c = 0; c < 4; c++) {
                float w2v = w2[(d0 + c) * HIDDEN + j];
                if (w1j > 0.f) {            // active for large x
                    A[c] = fmaf(w2v, w1j, A[c]);
                    C[c] = fmaf(w2v, b1j, C[c]);
                } else if (w1j == 0.f) {    // constant unit: relu(b1j)
                    C[c] = fmaf(w2v, fmaxf(b1j, 0.f), C[c]);
                }
            }
        }
        sA[q] = make_float4(A[0], A[1], A[2], A[3]);
        sC[q] = make_float4(C[0], C[1], C[2], C[3]);
        if (q == 0) sXg = xlo + 0.5f;       // margin swallows divide rounding
    }
    __syncthreads();

    const int q   = threadIdx.x & 15;
    const float4 A = sA[q];
    const float4 C = sC[q];
    const float  xg = sXg;

    // ---- 8 float4s per thread, coalesced per-iteration stride of 256 ----
    int base = blockIdx.x * (256 * IT) + threadIdx.x;
    #pragma unroll
    for (int k = 0; k < IT; k++) {
        int v = base + k * 256;
        if (v >= n_vec) break;
        int pos = v >> 4;

        float x = __ldg(&input_ids[pos]);
        int   m = __ldg(&type_mask[pos]);

        float4 r;
        if (m) {
            // L2-only gather; table stays L2-resident (stores evict-first)
            r = __ldcg(&emb_table[((int)x) * 16 + q]);
        } else {
            r = make_float4(fmaf(A.x, x, C.x), fmaf(A.y, x, C.y),
                            fmaf(A.z, x, C.z), fmaf(A.w, x, C.w));
            if (x < xg && q == 0) {          // rare: record for exact fixup
                int slot = atomicAdd(&g_fix_count, 1);
                g_fix_list[slot] = pos;
            }
        }
        __stcs(&out[v], r);                  // streaming store, evict-first
    }
}

__global__ void __launch_bounds__(256) fixup_kernel(
    const float* __restrict__ input_ids,
    const float* __restrict__ w1,
    const float* __restrict__ b1,
    const float* __restrict__ w2,
    const float* __restrict__ b2,
    float4* __restrict__ out)
{
    // Every block reads the count BEFORE signalling done; the last block to
    // arrive resets counters, so no block can miss its share.
    int n = g_fix_count;
    for (int i = blockIdx.x * blockDim.x + threadIdx.x; i < n;
         i += gridDim.x * blockDim.x) {
        int pos = g_fix_list[i];
        float x = input_ids[pos];

        float h[HIDDEN];
        #pragma unroll
        for (int j = 0; j < HIDDEN; j++)
            h[j] = fmaxf(fmaf(w1[j], x, b1[j]), 0.f);

        #pragma unroll
        for (int qq = 0; qq < 16; qq++) {
            float a[4];
            #pragma unroll
            for (int c = 0; c < 4; c++) {
                int d = qq * 4 + c;
                float s = b2[d];
                #pragma unroll
                for (int j = 0; j < HIDDEN; j++)
                    s = fmaf(w2[d * HIDDEN + j], h[j], s);
                a[c] = s;
            }
            out[pos * 16 + qq] = make_float4(a[0], a[1], a[2], a[3]);
        }
    }
    __syncthreads();
    if (threadIdx.x == 0) {
        __threadfence();
        int t = atomicAdd(&g_done, 1);
        if (t == gridDim.x - 1) {            // last block: reset for replay
            g_fix_count = 0;
            g_done = 0;
        }
    }
}

extern "C" void kernel_launch(void* const* d_in, const int* in_sizes, int n_in,
                              void* d_out, int out_size) {
    const float*  input_ids = (const float*)d_in[0];
    const int*    type_mask = (const int*)d_in[1];
    const float4* emb_table = (const float4*)d_in[2];
    const float*  w1        = (const float*)d_in[3];
    const float*  b1        = (const float*)d_in[4];
    const float*  w2        = (const float*)d_in[5];
    const float*  b2        = (const float*)d_in[6];
    float4* out = (float4*)d_out;

    int n_vec = out_size / 4;               // 8.4M float4s
    int per_block = 256 * IT;
    int blocks = (n_vec + per_block - 1) / per_block;   // 4096

    embedder_kernel<<<blocks, 256>>>(input_ids, type_mask, emb_table,
                                     w1, b1, w2, b2, out, n_vec);
    fixup_kernel<<<FIXUP_BLOCKS, 256>>>(input_ids, w1, b1, w2, b2, out);
}

// round 11
// speedup vs baseline: 1.4610x; 1.4610x over previous
#include <cuda_runtime.h>
#include <cuda_bf16.h>

// Embedder R9: SINGLE kernel. No prep, no fixup, no atomics, no device state.
//   Per-block prologue: threads 0..15 fold the MLP into affine sA/sC (+xguard);
//   all 256 threads stage w1/b1/b2/w2 into smem (4.4 KB).
//   Hot loop (8 float4/thread): token -> __ldcg 256B gather (table stays
//   L2-resident because output stores are __stcs evict-first);
//   numeric -> A*x+C (exact for x >= xguard).
//   Rare numeric x < xguard: recompute those 4 dims EXACTLY from smem inline
//   (per-dim accumulation, relu recomputed -> no h[] array, low reg pressure).
//   Always correct; rarity only affects speed.

#define HIDDEN 16
#define IT     8                      // float4s per thread

__global__ void __launch_bounds__(256) embedder_kernel(
    const float* __restrict__ input_ids,
    const int* __restrict__ type_mask,
    const float4* __restrict__ emb_table,   // [VOCAB][16] float4
    const float* __restrict__ w1,
    const float* __restrict__ b1,
    const float* __restrict__ w2,           // [64][16]
    const float* __restrict__ b2,
    float4* __restrict__ out,
    int n_vec)
{
    __shared__ float4 sA[16];
    __shared__ float4 sC[16];
    __shared__ float  sXg;
    __shared__ float  s_w1[HIDDEN];
    __shared__ float  s_b1[HIDDEN];
    __shared__ float  s_b2[64];
    __shared__ float  s_w2[64 * HIDDEN];    // 4 KB

    // ---- stage weights into smem (L1/L2-hot after block 0) ----
    {
        int t = threadIdx.x;
        if (t < HIDDEN) { s_w1[t] = w1[t]; s_b1[t] = b1[t]; }
        if (t < 64)      s_b2[t] = b2[t];
        // 1024 w2 floats / 256 threads = 4 each
        #pragma unroll
        for (int k = 0; k < 4; k++)
            s_w2[t + k * 256] = w2[t + k * 256];
    }

    // ---- per-block affine fold (threads 0..15) ----
    if (threadIdx.x < 16) {
        int q  = threadIdx.x;
        int d0 = q * 4;
        float A[4] = {0.f, 0.f, 0.f, 0.f};
        float C[4] = {b2[d0], b2[d0+1], b2[d0+2], b2[d0+3]};
        float xlo = -3.4e38f;
        #pragma unroll
        for (int j = 0; j < HIDDEN; j++) {
            float w1j = w1[j], b1j = b1[j];
            if (w1j != 0.f) xlo = fmaxf(xlo, -b1j / w1j);
            #pragma unroll
            for (int c = 0; c < 4; c++) {
                float w2v = w2[(d0 + c) * HIDDEN + j];
                if (w1j > 0.f) {            // active for large x
                    A[c] = fmaf(w2v, w1j, A[c]);
                    C[c] = fmaf(w2v, b1j, C[c]);
                } else if (w1j == 0.f) {    // constant unit: relu(b1j)
                    C[c] = fmaf(w2v, fmaxf(b1j, 0.f), C[c]);
                }
            }
        }
        sA[q] = make_float4(A[0], A[1], A[2], A[3]);
        sC[q] = make_float4(C[0], C[1], C[2], C[3]);
        if (q == 0) sXg = xlo + 0.5f;       // margin swallows divide rounding
    }
    __syncthreads();

    const int q   = threadIdx.x & 15;
    const int d0  = q * 4;
    const float4 A  = sA[q];
    const float4 C  = sC[q];
    const float  xg = sXg;

    // ---- 8 float4s per thread, coalesced per-iteration stride of 256 ----
    int base = blockIdx.x * (256 * IT) + threadIdx.x;
    #pragma unroll
    for (int k = 0; k < IT; k++) {
        int v = base + k * 256;
        if (v >= n_vec) break;
        int pos = v >> 4;

        float x = __ldg(&input_ids[pos]);
        int   m = __ldg(&type_mask[pos]);

        float4 r;
        if (m) {
            // L2-only gather; table stays L2-resident (stores evict-first)
            r = __ldcg(&emb_table[((int)x) * 16 + q]);
        } else {
            r = make_float4(fmaf(A.x, x, C.x), fmaf(A.y, x, C.y),
                            fmaf(A.z, x, C.z), fmaf(A.w, x, C.w));
            if (x < xg) {
                // rare: exact MLP for this thread's 4 dims, all from smem.
                // per-dim accumulation (relu recomputed) -> no h[] array.
                float acc[4];
                #pragma unroll
                for (int c = 0; c < 4; c++) {
                    float s = s_b2[d0 + c];
                    for (int j = 0; j < HIDDEN; j++) {
                        float h = fmaxf(fmaf(s_w1[j], x, s_b1[j]), 0.f);
                        s = fmaf(s_w2[(d0 + c) * HIDDEN + j], h, s);
                    }
                    acc[c] = s;
                }
                r = make_float4(acc[0], acc[1], acc[2], acc[3]);
            }
        }
        __stcs(&out[v], r);                  // streaming store, evict-first
    }
}

extern "C" void kernel_launch(void* const* d_in, const int* in_sizes, int n_in,
                              void* d_out, int out_size) {
    const float*  input_ids = (const float*)d_in[0];
    const int*    type_mask = (const int*)d_in[1];
    const float4* emb_table = (const float4*)d_in[2];
    const float*  w1        = (const float*)d_in[3];
    const float*  b1        = (const float*)d_in[4];
    const float*  w2        = (const float*)d_in[5];
    const float*  b2        = (const float*)d_in[6];
    float4* out = (float4*)d_out;

    int n_vec = out_size / 4;               // 8.4M float4s
    int per_block = 256 * IT;
    int blocks = (n_vec + per_block - 1) / per_block;   // 4096

    embedder_kernel<<<blocks, 256>>>(input_ids, type_mask, emb_table,
                                     w1, b1, w2, b2, out, n_vec);
}